// round 5
// baseline (speedup 1.0000x reference)
#include <cuda_runtime.h>
#include <math.h>

// Problem constants: NS = NT = 80, D = 512, N = 6400, kdiag = 79*79 = 6241.
#define NSd   80
#define Dd    512
#define Nn    6400
#define NBK   128

// ---------------- device scratch (no allocation allowed) ----------------
__device__ float g_e1[NSd * Dd];
__device__ float g_e2[NSd * Dd];
__device__ float g_m1[NSd * Dd];
__device__ float g_m2[NSd * Dd];
__device__ float g_x1[NSd * Dd];
__device__ float g_x2[NSd * Dd];
__device__ float g_y1[NSd * Dd];   // becomes e1n after normalize
__device__ float g_y2[NSd * Dd];   // becomes e2n after normalize
__device__ float g_Mp0[NSd * NSd];
__device__ float g_v[Nn];          // v[p] = Mp[p%80, p/80]
__device__ float g_inv[NBK * NBK]; // invL of current diagonal block, g_inv[j*128+c] = invL[j][c]

__device__ __forceinline__ float warp_sum(float s) {
#pragma unroll
    for (int o = 16; o > 0; o >>= 1) s += __shfl_xor_sync(0xffffffffu, s, o);
    return s;
}

// ---------------- phase 1: small embedding chain (unchanged, ~25us total) ----------------

__global__ void k_transpose(const float* __restrict__ us, const float* __restrict__ ut) {
    int idx = blockIdx.x * blockDim.x + threadIdx.x;
    if (idx < NSd * Dd) {
        int i = idx >> 9, d = idx & 511;
        g_e1[idx] = us[d * NSd + i];
        g_e2[idx] = ut[d * NSd + i];
    }
}

__global__ void k_mp0(const float* __restrict__ iou) {
    int i = blockIdx.x;
    int warp = threadIdx.x >> 5, lane = threadIdx.x & 31;
    const float* a = g_e1 + i * Dd;
    for (int j = warp; j < NSd; j += 4) {
        const float* b = g_e2 + j * Dd;
        float s = 0.f;
#pragma unroll 4
        for (int d = lane; d < Dd; d += 32) s += a[d] * b[d];
        s = warp_sum(s);
        if (lane == 0) g_Mp0[i * NSd + j] = s + iou[i * NSd + j];
    }
}

__global__ void k_m1m2() {
    int r = blockIdx.x, which = blockIdx.y;
    __shared__ float w[NSd];
    int tid = threadIdx.x;
    if (tid < NSd) w[tid] = (which == 0) ? g_Mp0[r * NSd + tid] : g_Mp0[tid * NSd + r];
    __syncthreads();
    const float* E = (which == 0) ? g_e2 : g_e1;
    float* out     = (which == 0) ? g_m1 : g_m2;
    float acc = 0.f;
#pragma unroll 8
    for (int t = 0; t < NSd; t++) acc += w[t] * E[t * Dd + tid];
    out[r * Dd + tid] = acc;
}

__global__ void k_lamprep() {
    int r = blockIdx.x, which = blockIdx.y;
    const float* e = ((which == 0) ? g_e1 : g_e2) + r * Dd;
    const float* m = ((which == 0) ? g_m1 : g_m2) + r * Dd;
    float* x       = ((which == 0) ? g_x1 : g_x2) + r * Dd;
    float se = 0.f, sm = 0.f;
    for (int d = threadIdx.x; d < Dd; d += 256) {
        float ev = e[d], mv = m[d];
        se += ev * ev; sm += mv * mv;
    }
    se = warp_sum(se); sm = warp_sum(sm);
    __shared__ float rs[8], rm[8], lamS;
    int warp = threadIdx.x >> 5, lane = threadIdx.x & 31;
    if (lane == 0) { rs[warp] = se; rm[warp] = sm; }
    __syncthreads();
    if (threadIdx.x == 0) {
        float SE = 0.f, SM = 0.f;
        for (int t = 0; t < 8; t++) { SE += rs[t]; SM += rm[t]; }
        lamS = sqrtf(SE) / sqrtf(SM);
    }
    __syncthreads();
    float lam = lamS;
    for (int d = threadIdx.x; d < Dd; d += 256) x[d] = e[d] + lam * m[d];
}

__global__ void k_gemmW(const float* __restrict__ W, const float* __restrict__ b) {
    int i = blockIdx.x, which = blockIdx.y;
    const float* X = ((which == 0) ? g_x1 : g_x2) + i * Dd;
    float* Y       = ((which == 0) ? g_y1 : g_y2) + i * Dd;
    __shared__ float xs[Dd];
    for (int d = threadIdx.x; d < Dd; d += 128) xs[d] = X[d];
    __syncthreads();
    int warp = threadIdx.x >> 5, lane = threadIdx.x & 31;
    for (int o = warp; o < Dd; o += 4) {
        const float* wr = W + o * Dd;
        float s = 0.f;
#pragma unroll 4
        for (int d = lane; d < Dd; d += 32) s += xs[d] * wr[d];
        s = warp_sum(s);
        if (lane == 0) Y[o] = fmaxf(s + b[o], 0.f);
    }
}

__global__ void k_norm() {
    int r = blockIdx.x, which = blockIdx.y;
    float* y = ((which == 0) ? g_y1 : g_y2) + r * Dd;
    float s = 0.f;
    for (int d = threadIdx.x; d < Dd; d += 256) { float v = y[d]; s += v * v; }
    s = warp_sum(s);
    __shared__ float rs[8]; __shared__ float invS;
    int warp = threadIdx.x >> 5, lane = threadIdx.x & 31;
    if (lane == 0) rs[warp] = s;
    __syncthreads();
    if (threadIdx.x == 0) {
        float S = 0.f;
        for (int t = 0; t < 8; t++) S += rs[t];
        invS = 1.0f / fmaxf(sqrtf(S), 1e-12f);
    }
    __syncthreads();
    float inv = invS;
    for (int d = threadIdx.x; d < Dd; d += 256) y[d] *= inv;
}

__global__ void k_mp_thr(float* __restrict__ Mp_out, float* __restrict__ flag_out,
                         const float* __restrict__ kf, const float* __restrict__ iou,
                         const float* __restrict__ thrp) {
    int i = blockIdx.x;
    int warp = threadIdx.x >> 5, lane = threadIdx.x & 31;
    const float* a = g_y1 + i * Dd;
    float th = thrp[0];
    for (int j = warp; j < NSd; j += 4) {
        const float* b = g_y2 + j * Dd;
        float s = 0.f;
#pragma unroll 4
        for (int d = lane; d < Dd; d += 32) s += a[d] * b[d];
        s = warp_sum(s);
        if (lane == 0) {
            Mp_out[i * NSd + j] = s;
            g_v[j * NSd + i] = s;
            float fl = (kf[i * NSd + j] == -1.0f || iou[i * NSd + j] == 0.0f || s < th) ? 1.0f : 0.0f;
            flag_out[i * NSd + j] = fl;
        }
    }
}

// ---------------- phase 2: build A directly into the L output region ----------------
// A[p,q] = 6241 (p==q); -0.5*(v[p]+v[q]) if (s1!=s2 && t1!=t2) and q<p; upper triangle = 0.
__global__ void k_buildA(float* __restrict__ L) {
    int p = blockIdx.x;
    int s1 = p % NSd, t1 = p / NSd;
    float vp = g_v[p];
    float* row = L + (size_t)p * Nn;
    for (int q = threadIdx.x; q < Nn; q += 256) {
        float val = 0.f;
        if (q == p) val = 6241.0f;
        else if (q < p) {
            int s2 = q % NSd, t2 = q / NSd;
            if (s1 != s2 && t1 != t2) val = -0.5f * (vp + g_v[q]);
        }
        row[q] = val;
    }
}

// ---------------- phase 3: blocked Cholesky (NB=128, in place, lower) ----------------

// Factor the 128x128 diagonal block at (j,j) AND compute its triangular inverse
// into g_inv. One block, 512 threads, dynamic shared:
//   Lsh[128*129] | colbuf[128] | xbuf[16*128]
__global__ __launch_bounds__(512) void potf2_128(float* __restrict__ L, int j) {
    extern __shared__ float dsh[];
    float* Lsh    = dsh;                 // 128*129 = 16512
    float* colbuf = dsh + 128 * 129;     // 128
    float* xbuf   = colbuf + 128;        // 16*128

    int tid = threadIdx.x;
    float* A = L + (size_t)j * Nn + j;

    // load full 128x128 block (upper is zeros from buildA; never read anyway)
    for (int idx = tid; idx < 128 * 128; idx += 512) {
        int r = idx >> 7, c = idx & 127;
        Lsh[r * 129 + c] = A[(size_t)r * Nn + c];
    }
    __syncthreads();

    int tq   = tid & 127;
    int trow = tid >> 7;     // 0..3

    for (int c = 0; c < 128; c++) {
        // stage the (unscaled) pivot column
        if (tid < 128) colbuf[tid] = Lsh[tid * 129 + c];
        __syncthreads();
        float dv  = sqrtf(colbuf[c]);
        float inv = 1.0f / dv;
        float i2  = inv * inv;
        // scale column c (final values) + rank-1 trailing update folded with inv^2
        if (tid < 128) {
            if (tid > c)       Lsh[tid * 129 + c] = colbuf[tid] * inv;
            else if (tid == c) Lsh[c * 129 + c]   = dv;
        }
        if (tq > c) {
            float xq = colbuf[tq] * i2;
            for (int rr = c + 1 + trow; rr < 128; rr += 4)
                Lsh[rr * 129 + tq] -= colbuf[rr] * xq;
        }
        __syncthreads();
    }

    // write back lower triangle
    for (int idx = tid; idx < 128 * 128; idx += 512) {
        int r = idx >> 7, c = idx & 127;
        if (c <= r) A[(size_t)r * Nn + c] = Lsh[r * 129 + c];
    }

    // ---- TRTRI: invL columns via warp-per-column forward substitution ----
    int warpid = tid >> 5, lane = tid & 31;
    float* xb = xbuf + warpid * 128;
    for (int c = warpid; c < 128; c += 16) {
        if (lane == 0) xb[c] = 1.0f / Lsh[c * 129 + c];
        __syncwarp();
        for (int jj = c + 1; jj < 128; jj++) {
            float s = 0.f;
            for (int k = c + lane; k < jj; k += 32) s += Lsh[jj * 129 + k] * xb[k];
            s = warp_sum(s);
            if (lane == 0) xb[jj] = -s / Lsh[jj * 129 + jj];
            __syncwarp();
        }
        // g_inv[row * 128 + col] = invL[row][col]; zero the strict upper part
        for (int jj = c + lane; jj < 128; jj += 32) g_inv[jj * 128 + c] = xb[jj];
        for (int jj = lane; jj < c; jj += 32)       g_inv[jj * 128 + c] = 0.f;
        __syncwarp();
    }
}

// Panel solve as GEMM: X = B * invL^T  (B = panel rows j+128.., cols j..j+128).
// X[r][c] = sum_k B[r][k] * g_inv[c*128+k]. 128-row tile per block, 256 thr, 8x8 micro.
__global__ __launch_bounds__(256) void trsmg_k(float* __restrict__ L, int j, int M) {
    int row0 = blockIdx.x * 128;
    float* __restrict__ B = L + (size_t)(j + NBK) * Nn + j;
    __shared__ float As[16][132];
    __shared__ float Bs[16][132];
    int tid = threadIdx.x;
    float acc[8][8];
#pragma unroll
    for (int u = 0; u < 8; u++)
#pragma unroll
        for (int v = 0; v < 8; v++) acc[u][v] = 0.f;

    int ty = tid >> 4, tx = tid & 15;
    int rr = ty * 8, cc = tx * 8;

    for (int kk = 0; kk < NBK; kk += 16) {
#pragma unroll
        for (int rep = 0; rep < 2; rep++) {
            int f4 = tid + rep * 256;
            int i  = f4 >> 2;
            int k4 = (f4 & 3) << 2;
            float4 av = make_float4(0.f, 0.f, 0.f, 0.f);
            if (row0 + i < M) av = *(const float4*)(B + (size_t)(row0 + i) * Nn + kk + k4);
            float4 bv = *(const float4*)(g_inv + i * 128 + kk + k4);
            As[k4 + 0][i] = av.x; As[k4 + 1][i] = av.y; As[k4 + 2][i] = av.z; As[k4 + 3][i] = av.w;
            Bs[k4 + 0][i] = bv.x; Bs[k4 + 1][i] = bv.y; Bs[k4 + 2][i] = bv.z; Bs[k4 + 3][i] = bv.w;
        }
        __syncthreads();
#pragma unroll
        for (int k = 0; k < 16; k++) {
            float a[8], bq[8];
            *(float4*)&a[0]  = *(const float4*)&As[k][rr];
            *(float4*)&a[4]  = *(const float4*)&As[k][rr + 4];
            *(float4*)&bq[0] = *(const float4*)&Bs[k][cc];
            *(float4*)&bq[4] = *(const float4*)&Bs[k][cc + 4];
#pragma unroll
            for (int u = 0; u < 8; u++)
#pragma unroll
                for (int v = 0; v < 8; v++) acc[u][v] += a[u] * bq[v];
        }
        __syncthreads();
    }
    // overwrite panel in place (block writes only its own rows; all reads done)
#pragma unroll
    for (int u = 0; u < 8; u++) {
        int gr = row0 + rr + u;
        if (gr < M) {
            float* bp = B + (size_t)gr * Nn + cc;
            float4 c0, c1;
            c0.x = acc[u][0]; c0.y = acc[u][1]; c0.z = acc[u][2]; c0.w = acc[u][3];
            c1.x = acc[u][4]; c1.y = acc[u][5]; c1.z = acc[u][6]; c1.w = acc[u][7];
            *(float4*)bp = c0;
            *(float4*)(bp + 4) = c1;
        }
    }
}

// Trailing update: C -= P * P^T, P = [M x 128] solved panel. Lower block tiles only.
__global__ __launch_bounds__(256) void syrk_k(float* __restrict__ L, int j, int M) {
    int bx = blockIdx.x, by = blockIdx.y;
    if (by < bx) return;
    const float* __restrict__ P = L + (size_t)(j + NBK) * Nn + j;
    float* __restrict__ C = L + (size_t)(j + NBK) * Nn + (j + NBK);
    int row0 = by * 128, col0 = bx * 128;
    __shared__ float As[16][132];
    __shared__ float Bs[16][132];
    int tid = threadIdx.x;
    float acc[8][8];
#pragma unroll
    for (int u = 0; u < 8; u++)
#pragma unroll
        for (int v = 0; v < 8; v++) acc[u][v] = 0.f;

    int ty = tid >> 4, tx = tid & 15;
    int rr = ty * 8, cc = tx * 8;

    for (int kk = 0; kk < NBK; kk += 16) {
#pragma unroll
        for (int rep = 0; rep < 2; rep++) {
            int f4 = tid + rep * 256;
            int i  = f4 >> 2;
            int k4 = (f4 & 3) << 2;
            float4 av = make_float4(0.f, 0.f, 0.f, 0.f);
            float4 bv = make_float4(0.f, 0.f, 0.f, 0.f);
            if (row0 + i < M) av = *(const float4*)(P + (size_t)(row0 + i) * Nn + kk + k4);
            if (col0 + i < M) bv = *(const float4*)(P + (size_t)(col0 + i) * Nn + kk + k4);
            As[k4 + 0][i] = av.x; As[k4 + 1][i] = av.y; As[k4 + 2][i] = av.z; As[k4 + 3][i] = av.w;
            Bs[k4 + 0][i] = bv.x; Bs[k4 + 1][i] = bv.y; Bs[k4 + 2][i] = bv.z; Bs[k4 + 3][i] = bv.w;
        }
        __syncthreads();
#pragma unroll
        for (int k = 0; k < 16; k++) {
            float a[8], bq[8];
            *(float4*)&a[0]  = *(const float4*)&As[k][rr];
            *(float4*)&a[4]  = *(const float4*)&As[k][rr + 4];
            *(float4*)&bq[0] = *(const float4*)&Bs[k][cc];
            *(float4*)&bq[4] = *(const float4*)&Bs[k][cc + 4];
#pragma unroll
            for (int u = 0; u < 8; u++)
#pragma unroll
                for (int v = 0; v < 8; v++) acc[u][v] += a[u] * bq[v];
        }
        __syncthreads();
    }

    if (by > bx) {
#pragma unroll
        for (int u = 0; u < 8; u++) {
            int gr = row0 + rr + u;
            if (gr < M) {
                float* cp = C + (size_t)gr * Nn + col0 + cc;
                float4 c0 = *(float4*)cp;
                float4 c1 = *(float4*)(cp + 4);
                c0.x -= acc[u][0]; c0.y -= acc[u][1]; c0.z -= acc[u][2]; c0.w -= acc[u][3];
                c1.x -= acc[u][4]; c1.y -= acc[u][5]; c1.z -= acc[u][6]; c1.w -= acc[u][7];
                *(float4*)cp = c0;
                *(float4*)(cp + 4) = c1;
            }
        }
    } else {
        // diagonal tile: keep upper triangle untouched (holds the output zeros)
#pragma unroll
        for (int u = 0; u < 8; u++) {
            int gr = row0 + rr + u;
            if (gr < M) {
#pragma unroll
                for (int v = 0; v < 8; v++) {
                    int gc = col0 + cc + v;
                    if (gc <= gr) C[(size_t)gr * Nn + gc] -= acc[u][v];
                }
            }
        }
    }
}

// ---------------- launch ----------------
extern "C" void kernel_launch(void* const* d_in, const int* in_sizes, int n_in,
                              void* d_out, int out_size) {
    (void)in_sizes; (void)n_in; (void)out_size;
    const float* U_src = (const float*)d_in[0];
    const float* U_tgt = (const float*)d_in[1];
    const float* kf    = (const float*)d_in[2];
    const float* thrp  = (const float*)d_in[3];
    const float* iou   = (const float*)d_in[4];
    const float* W     = (const float*)d_in[5];
    const float* b     = (const float*)d_in[6];

    float* out      = (float*)d_out;
    float* Mp_out   = out;                       // [80*80]
    float* Lm       = out + NSd * NSd;           // [6400*6400]
    float* flag_out = out + NSd * NSd + Nn * Nn; // [80*80]

    const int potf2_smem = (128 * 129 + 128 + 16 * 128) * (int)sizeof(float); // 74752 B
    cudaFuncSetAttribute(potf2_128, cudaFuncAttributeMaxDynamicSharedMemorySize, potf2_smem);

    k_transpose<<<(NSd * Dd + 255) / 256, 256>>>(U_src, U_tgt);
    k_mp0<<<NSd, 128>>>(iou);
    k_m1m2<<<dim3(NSd, 2), 512>>>();
    k_lamprep<<<dim3(NSd, 2), 256>>>();
    k_gemmW<<<dim3(NSd, 2), 128>>>(W, b);
    k_norm<<<dim3(NSd, 2), 256>>>();
    k_mp_thr<<<NSd, 128>>>(Mp_out, flag_out, kf, iou, thrp);
    k_buildA<<<Nn, 256>>>(Lm);

    for (int j = 0; j < Nn; j += NBK) {
        potf2_128<<<1, 512, potf2_smem>>>(Lm, j);
        int M = Nn - j - NBK;
        if (M > 0) {
            trsmg_k<<<(M + 127) / 128, 256>>>(Lm, j, M);
            dim3 g((M + 127) / 128, (M + 127) / 128);
            syrk_k<<<g, 256>>>(Lm, j, M);
        }
    }
}

// round 6
// speedup vs baseline: 1.7796x; 1.7796x over previous
#include <cuda_runtime.h>
#include <math.h>

// Problem constants: NS = NT = 80, D = 512, N = 6400, kdiag = 79*79 = 6241.
#define NSd   80
#define Dd    512
#define Nn    6400

// ---------------- device scratch (no allocation allowed) ----------------
__device__ float g_e1[NSd * Dd];
__device__ float g_e2[NSd * Dd];
__device__ float g_m1[NSd * Dd];
__device__ float g_m2[NSd * Dd];
__device__ float g_x1[NSd * Dd];
__device__ float g_x2[NSd * Dd];
__device__ float g_y1[NSd * Dd];
__device__ float g_y2[NSd * Dd];
__device__ float g_Mp0[NSd * NSd];
__device__ float g_v[Nn];           // v[p] = Mp[p%80, p/80]
__device__ float g_inv[64 * 64];    // invL of current diag block: g_inv[r*64+c] = invL[r][c]

__device__ __forceinline__ float warp_sum(float s) {
#pragma unroll
    for (int o = 16; o > 0; o >>= 1) s += __shfl_xor_sync(0xffffffffu, s, o);
    return s;
}

// ---------------- phase 1: small embedding chain (~25us total) ----------------

__global__ void k_transpose(const float* __restrict__ us, const float* __restrict__ ut) {
    int idx = blockIdx.x * blockDim.x + threadIdx.x;
    if (idx < NSd * Dd) {
        int i = idx >> 9, d = idx & 511;
        g_e1[idx] = us[d * NSd + i];
        g_e2[idx] = ut[d * NSd + i];
    }
}

__global__ void k_mp0(const float* __restrict__ iou) {
    int i = blockIdx.x;
    int warp = threadIdx.x >> 5, lane = threadIdx.x & 31;
    const float* a = g_e1 + i * Dd;
    for (int j = warp; j < NSd; j += 4) {
        const float* b = g_e2 + j * Dd;
        float s = 0.f;
#pragma unroll 4
        for (int d = lane; d < Dd; d += 32) s += a[d] * b[d];
        s = warp_sum(s);
        if (lane == 0) g_Mp0[i * NSd + j] = s + iou[i * NSd + j];
    }
}

__global__ void k_m1m2() {
    int r = blockIdx.x, which = blockIdx.y;
    __shared__ float w[NSd];
    int tid = threadIdx.x;
    if (tid < NSd) w[tid] = (which == 0) ? g_Mp0[r * NSd + tid] : g_Mp0[tid * NSd + r];
    __syncthreads();
    const float* E = (which == 0) ? g_e2 : g_e1;
    float* out     = (which == 0) ? g_m1 : g_m2;
    float acc = 0.f;
#pragma unroll 8
    for (int t = 0; t < NSd; t++) acc += w[t] * E[t * Dd + tid];
    out[r * Dd + tid] = acc;
}

__global__ void k_lamprep() {
    int r = blockIdx.x, which = blockIdx.y;
    const float* e = ((which == 0) ? g_e1 : g_e2) + r * Dd;
    const float* m = ((which == 0) ? g_m1 : g_m2) + r * Dd;
    float* x       = ((which == 0) ? g_x1 : g_x2) + r * Dd;
    float se = 0.f, sm = 0.f;
    for (int d = threadIdx.x; d < Dd; d += 256) {
        float ev = e[d], mv = m[d];
        se += ev * ev; sm += mv * mv;
    }
    se = warp_sum(se); sm = warp_sum(sm);
    __shared__ float rs[8], rm[8], lamS;
    int warp = threadIdx.x >> 5, lane = threadIdx.x & 31;
    if (lane == 0) { rs[warp] = se; rm[warp] = sm; }
    __syncthreads();
    if (threadIdx.x == 0) {
        float SE = 0.f, SM = 0.f;
        for (int t = 0; t < 8; t++) { SE += rs[t]; SM += rm[t]; }
        lamS = sqrtf(SE) / sqrtf(SM);
    }
    __syncthreads();
    float lam = lamS;
    for (int d = threadIdx.x; d < Dd; d += 256) x[d] = e[d] + lam * m[d];
}

__global__ void k_gemmW(const float* __restrict__ W, const float* __restrict__ b) {
    int i = blockIdx.x, which = blockIdx.y;
    const float* X = ((which == 0) ? g_x1 : g_x2) + i * Dd;
    float* Y       = ((which == 0) ? g_y1 : g_y2) + i * Dd;
    __shared__ float xs[Dd];
    for (int d = threadIdx.x; d < Dd; d += 128) xs[d] = X[d];
    __syncthreads();
    int warp = threadIdx.x >> 5, lane = threadIdx.x & 31;
    for (int o = warp; o < Dd; o += 4) {
        const float* wr = W + o * Dd;
        float s = 0.f;
#pragma unroll 4
        for (int d = lane; d < Dd; d += 32) s += xs[d] * wr[d];
        s = warp_sum(s);
        if (lane == 0) Y[o] = fmaxf(s + b[o], 0.f);
    }
}

__global__ void k_norm() {
    int r = blockIdx.x, which = blockIdx.y;
    float* y = ((which == 0) ? g_y1 : g_y2) + r * Dd;
    float s = 0.f;
    for (int d = threadIdx.x; d < Dd; d += 256) { float v = y[d]; s += v * v; }
    s = warp_sum(s);
    __shared__ float rs[8]; __shared__ float invS;
    int warp = threadIdx.x >> 5, lane = threadIdx.x & 31;
    if (lane == 0) rs[warp] = s;
    __syncthreads();
    if (threadIdx.x == 0) {
        float S = 0.f;
        for (int t = 0; t < 8; t++) S += rs[t];
        invS = 1.0f / fmaxf(sqrtf(S), 1e-12f);
    }
    __syncthreads();
    float inv = invS;
    for (int d = threadIdx.x; d < Dd; d += 256) y[d] *= inv;
}

__global__ void k_mp_thr(float* __restrict__ Mp_out, float* __restrict__ flag_out,
                         const float* __restrict__ kf, const float* __restrict__ iou,
                         const float* __restrict__ thrp) {
    int i = blockIdx.x;
    int warp = threadIdx.x >> 5, lane = threadIdx.x & 31;
    const float* a = g_y1 + i * Dd;
    float th = thrp[0];
    for (int j = warp; j < NSd; j += 4) {
        const float* b = g_y2 + j * Dd;
        float s = 0.f;
#pragma unroll 4
        for (int d = lane; d < Dd; d += 32) s += a[d] * b[d];
        s = warp_sum(s);
        if (lane == 0) {
            Mp_out[i * NSd + j] = s;
            g_v[j * NSd + i] = s;
            float fl = (kf[i * NSd + j] == -1.0f || iou[i * NSd + j] == 0.0f || s < th) ? 1.0f : 0.0f;
            flag_out[i * NSd + j] = fl;
        }
    }
}

// ---------------- phase 2: build A directly into the L output region ----------------
__global__ void k_buildA(float* __restrict__ L) {
    int p = blockIdx.x;
    int s1 = p % NSd, t1 = p / NSd;
    float vp = g_v[p];
    float* row = L + (size_t)p * Nn;
    for (int q = threadIdx.x; q < Nn; q += 256) {
        float val = 0.f;
        if (q == p) val = 6241.0f;
        else if (q < p) {
            int s2 = q % NSd, t2 = q / NSd;
            if (s1 != s2 && t1 != t2) val = -0.5f * (vp + g_v[q]);
        }
        row[q] = val;
    }
}

// ---------------- phase 3: blocked Cholesky (NB=64, fused diag factorization) -----------

// Factor the 64x64 block at global pointer A (leading dim Nn) in place (lower),
// and write its triangular inverse into g_inv. Requires 256 threads and
// sbuf of >= 64*65 + 64 floats. Called by potf2_first and by syrk block (0,0).
__device__ void fact64(float* __restrict__ A, float* __restrict__ sbuf) {
    float* Lsh    = sbuf;            // 64*65 = 4160
    float* colbuf = sbuf + 64 * 65;  // 64
    int tid = threadIdx.x;

    for (int idx = tid; idx < 64 * 64; idx += 256) {
        int r = idx >> 6, c = idx & 63;
        if (c <= r) Lsh[r * 65 + c] = A[(size_t)r * Nn + c];
    }
    __syncthreads();

    int tq = tid & 63, trow = tid >> 6;   // 64 cols x 4 row-stripes
    for (int c = 0; c < 64; c++) {
        if (tid < 64) colbuf[tid] = Lsh[tid * 65 + c];
        __syncthreads();
        float dv  = sqrtf(colbuf[c]);
        float inv = 1.0f / dv;
        float i2  = inv * inv;
        if (tid < 64) {
            if (tid > c)       Lsh[tid * 65 + c] = colbuf[tid] * inv;
            else if (tid == c) Lsh[c * 65 + c]   = dv;
        }
        if (tq > c) {
            float xq = colbuf[tq] * i2;
            for (int rr = c + 1 + trow; rr < 64; rr += 4)
                Lsh[rr * 65 + tq] -= colbuf[rr] * xq;
        }
        __syncthreads();
    }

    for (int idx = tid; idx < 64 * 64; idx += 256) {
        int r = idx >> 6, c = idx & 63;
        if (c <= r) A[(size_t)r * Nn + c] = Lsh[r * 65 + c];
    }

    // reciprocal diagonal (reuse colbuf)
    if (tid < 64) colbuf[tid] = 1.0f / Lsh[tid * 65 + tid];
    __syncthreads();

    // TRTRI: one thread per column, sequential forward substitution.
    if (tid < 64) {
        int c = tid;
        float x[64];
        x[c] = colbuf[c];
        for (int jj = c + 1; jj < 64; jj++) {
            float s0 = 0.f, s1 = 0.f, s2 = 0.f, s3 = 0.f;
            int k = c;
            for (; k + 3 < jj; k += 4) {
                s0 += Lsh[jj * 65 + k + 0] * x[k + 0];
                s1 += Lsh[jj * 65 + k + 1] * x[k + 1];
                s2 += Lsh[jj * 65 + k + 2] * x[k + 2];
                s3 += Lsh[jj * 65 + k + 3] * x[k + 3];
            }
            for (; k < jj; k++) s0 += Lsh[jj * 65 + k] * x[k];
            x[jj] = -((s0 + s1) + (s2 + s3)) * colbuf[jj];
        }
        for (int jj = 0; jj < 64; jj++)
            g_inv[jj * 64 + c] = (jj >= c) ? x[jj] : 0.f;
    }
}

__global__ __launch_bounds__(256) void potf2_first(float* __restrict__ L) {
    __shared__ float sbuf[64 * 65 + 64];
    fact64(L, sbuf);
}

// Panel solve as GEMM: X = B * invL^T.  B = rows j+64.., cols j..j+64, in place.
// 128-row tile per block, 256 threads, 4x8 micro-tile (output 128x64).
__global__ __launch_bounds__(256) void trsm64_k(float* __restrict__ L, int j, int M) {
    int row0 = blockIdx.x * 128;
    float* __restrict__ B = L + (size_t)(j + 64) * Nn + j;
    __shared__ float As[16][132];
    __shared__ float Bs[16][68];
    int tid = threadIdx.x;
    float acc[4][8];
#pragma unroll
    for (int u = 0; u < 4; u++)
#pragma unroll
        for (int v = 0; v < 8; v++) acc[u][v] = 0.f;

    int ty = tid >> 3, tx = tid & 7;     // ty 0..31, tx 0..7
    int rr = ty * 4, cc = tx * 8;

    for (int kk = 0; kk < 64; kk += 16) {
#pragma unroll
        for (int rep = 0; rep < 2; rep++) {
            int f4 = tid + rep * 256;
            int i  = f4 >> 2;
            int k4 = (f4 & 3) << 2;
            float4 av = make_float4(0.f, 0.f, 0.f, 0.f);
            if (row0 + i < M) av = *(const float4*)(B + (size_t)(row0 + i) * Nn + kk + k4);
            As[k4 + 0][i] = av.x; As[k4 + 1][i] = av.y; As[k4 + 2][i] = av.z; As[k4 + 3][i] = av.w;
        }
        {
            int ci = tid >> 2;
            int k4 = (tid & 3) << 2;
            float4 bv = *(const float4*)(g_inv + ci * 64 + kk + k4);
            Bs[k4 + 0][ci] = bv.x; Bs[k4 + 1][ci] = bv.y; Bs[k4 + 2][ci] = bv.z; Bs[k4 + 3][ci] = bv.w;
        }
        __syncthreads();
#pragma unroll
        for (int k = 0; k < 16; k++) {
            float a[4], bq[8];
            *(float4*)&a[0]  = *(const float4*)&As[k][rr];
            *(float4*)&bq[0] = *(const float4*)&Bs[k][cc];
            *(float4*)&bq[4] = *(const float4*)&Bs[k][cc + 4];
#pragma unroll
            for (int u = 0; u < 4; u++)
#pragma unroll
                for (int v = 0; v < 8; v++) acc[u][v] += a[u] * bq[v];
        }
        __syncthreads();
    }
#pragma unroll
    for (int u = 0; u < 4; u++) {
        int gr = row0 + rr + u;
        if (gr < M) {
            float* bp = B + (size_t)gr * Nn + cc;
            float4 c0, c1;
            c0.x = acc[u][0]; c0.y = acc[u][1]; c0.z = acc[u][2]; c0.w = acc[u][3];
            c1.x = acc[u][4]; c1.y = acc[u][5]; c1.z = acc[u][6]; c1.w = acc[u][7];
            *(float4*)bp = c0;
            *(float4*)(bp + 4) = c1;
        }
    }
}

// Trailing update: C -= P * P^T, P = [M x 64] solved panel. Lower block tiles only.
// Block (0,0) additionally factors the next 64x64 diagonal block (fused potf2+trtri).
__global__ __launch_bounds__(256) void syrk_k(float* __restrict__ L, int j, int M) {
    int bx = blockIdx.x, by = blockIdx.y;
    if (by < bx) return;
    const float* __restrict__ P = L + (size_t)(j + 64) * Nn + j;
    float* __restrict__ C = L + (size_t)(j + 64) * Nn + (j + 64);
    int row0 = by * 128, col0 = bx * 128;

    __shared__ float sbuf[2 * 16 * 132];   // 4224 floats: As|Bs, reused by fact64
    float (*As)[132] = (float(*)[132])sbuf;
    float (*Bs)[132] = (float(*)[132])(sbuf + 16 * 132);

    int tid = threadIdx.x;
    float acc[8][8];
#pragma unroll
    for (int u = 0; u < 8; u++)
#pragma unroll
        for (int v = 0; v < 8; v++) acc[u][v] = 0.f;

    int ty = tid >> 4, tx = tid & 15;
    int rr = ty * 8, cc = tx * 8;

    for (int kk = 0; kk < 64; kk += 16) {
#pragma unroll
        for (int rep = 0; rep < 2; rep++) {
            int f4 = tid + rep * 256;
            int i  = f4 >> 2;
            int k4 = (f4 & 3) << 2;
            float4 av = make_float4(0.f, 0.f, 0.f, 0.f);
            float4 bv = make_float4(0.f, 0.f, 0.f, 0.f);
            if (row0 + i < M) av = *(const float4*)(P + (size_t)(row0 + i) * Nn + kk + k4);
            if (col0 + i < M) bv = *(const float4*)(P + (size_t)(col0 + i) * Nn + kk + k4);
            As[k4 + 0][i] = av.x; As[k4 + 1][i] = av.y; As[k4 + 2][i] = av.z; As[k4 + 3][i] = av.w;
            Bs[k4 + 0][i] = bv.x; Bs[k4 + 1][i] = bv.y; Bs[k4 + 2][i] = bv.z; Bs[k4 + 3][i] = bv.w;
        }
        __syncthreads();
#pragma unroll
        for (int k = 0; k < 16; k++) {
            float a[8], bq[8];
            *(float4*)&a[0]  = *(const float4*)&As[k][rr];
            *(float4*)&a[4]  = *(const float4*)&As[k][rr + 4];
            *(float4*)&bq[0] = *(const float4*)&Bs[k][cc];
            *(float4*)&bq[4] = *(const float4*)&Bs[k][cc + 4];
#pragma unroll
            for (int u = 0; u < 8; u++)
#pragma unroll
                for (int v = 0; v < 8; v++) acc[u][v] += a[u] * bq[v];
        }
        __syncthreads();
    }

    if (by > bx) {
#pragma unroll
        for (int u = 0; u < 8; u++) {
            int gr = row0 + rr + u;
            if (gr < M) {
                float* cp = C + (size_t)gr * Nn + col0 + cc;
                float4 c0 = *(float4*)cp;
                float4 c1 = *(float4*)(cp + 4);
                c0.x -= acc[u][0]; c0.y -= acc[u][1]; c0.z -= acc[u][2]; c0.w -= acc[u][3];
                c1.x -= acc[u][4]; c1.y -= acc[u][5]; c1.z -= acc[u][6]; c1.w -= acc[u][7];
                *(float4*)cp = c0;
                *(float4*)(cp + 4) = c1;
            }
        }
    } else {
        // diagonal tile: keep upper triangle untouched (holds the output zeros)
#pragma unroll
        for (int u = 0; u < 8; u++) {
            int gr = row0 + rr + u;
            if (gr < M) {
#pragma unroll
                for (int v = 0; v < 8; v++) {
                    int gc = col0 + cc + v;
                    if (gc <= gr) C[(size_t)gr * Nn + gc] -= acc[u][v];
                }
            }
        }
    }

    // Fused next-step diagonal factorization: block (0,0) owns tile containing
    // D(j+64) (top-left 64x64 of C, fully updated by this block's stores above).
    if (bx == 0 && by == 0) {
        __syncthreads();   // block-level visibility of this block's global stores
        fact64(C, sbuf);
    }
}

// ---------------- launch ----------------
extern "C" void kernel_launch(void* const* d_in, const int* in_sizes, int n_in,
                              void* d_out, int out_size) {
    (void)in_sizes; (void)n_in; (void)out_size;
    const float* U_src = (const float*)d_in[0];
    const float* U_tgt = (const float*)d_in[1];
    const float* kf    = (const float*)d_in[2];
    const float* thrp  = (const float*)d_in[3];
    const float* iou   = (const float*)d_in[4];
    const float* W     = (const float*)d_in[5];
    const float* b     = (const float*)d_in[6];

    float* out      = (float*)d_out;
    float* Mp_out   = out;                       // [80*80]
    float* Lm       = out + NSd * NSd;           // [6400*6400]
    float* flag_out = out + NSd * NSd + Nn * Nn; // [80*80]

    k_transpose<<<(NSd * Dd + 255) / 256, 256>>>(U_src, U_tgt);
    k_mp0<<<NSd, 128>>>(iou);
    k_m1m2<<<dim3(NSd, 2), 512>>>();
    k_lamprep<<<dim3(NSd, 2), 256>>>();
    k_gemmW<<<dim3(NSd, 2), 128>>>(W, b);
    k_norm<<<dim3(NSd, 2), 256>>>();
    k_mp_thr<<<NSd, 128>>>(Mp_out, flag_out, kf, iou, thrp);
    k_buildA<<<Nn, 256>>>(Lm);

    potf2_first<<<1, 256>>>(Lm);
    for (int j = 0; j + 64 < Nn; j += 64) {
        int M = Nn - j - 64;
        trsm64_k<<<(M + 127) / 128, 256>>>(Lm, j, M);
        dim3 g((M + 127) / 128, (M + 127) / 128);
        syrk_k<<<g, 256>>>(Lm, j, M);   // block (0,0) also factors D(j+64)
    }
}

// round 7
// speedup vs baseline: 1.8225x; 1.0241x over previous
#include <cuda_runtime.h>
#include <math.h>

// Problem constants: NS = NT = 80, D = 512, N = 6400, kdiag = 79*79 = 6241.
#define NSd   80
#define Dd    512
#define Nn    6400
#define GPERS 148   // persistent grid = #SMs on B200; occupancy>=2 guarantees residency

// ---------------- device scratch (no allocation allowed) ----------------
__device__ float g_e1[NSd * Dd];
__device__ float g_e2[NSd * Dd];
__device__ float g_m1[NSd * Dd];
__device__ float g_m2[NSd * Dd];
__device__ float g_x1[NSd * Dd];
__device__ float g_x2[NSd * Dd];
__device__ float g_y1[NSd * Dd];
__device__ float g_y2[NSd * Dd];
__device__ float g_Mp0[NSd * NSd];
__device__ float g_v[Nn];           // v[p] = Mp[p%80, p/80]
__device__ float g_inv[64 * 64];    // invL of current diag block
__device__ int   g_cnt;             // grid barrier arrival counter
__device__ int   g_gen;             // grid barrier generation

__device__ __forceinline__ float warp_sum(float s) {
#pragma unroll
    for (int o = 16; o > 0; o >>= 1) s += __shfl_xor_sync(0xffffffffu, s, o);
    return s;
}

// ---------------- phase 1: small embedding chain (~25us total) ----------------

__global__ void k_transpose(const float* __restrict__ us, const float* __restrict__ ut) {
    int idx = blockIdx.x * blockDim.x + threadIdx.x;
    if (idx < NSd * Dd) {
        int i = idx >> 9, d = idx & 511;
        g_e1[idx] = us[d * NSd + i];
        g_e2[idx] = ut[d * NSd + i];
    }
}

__global__ void k_mp0(const float* __restrict__ iou) {
    int i = blockIdx.x;
    int warp = threadIdx.x >> 5, lane = threadIdx.x & 31;
    const float* a = g_e1 + i * Dd;
    for (int j = warp; j < NSd; j += 4) {
        const float* b = g_e2 + j * Dd;
        float s = 0.f;
#pragma unroll 4
        for (int d = lane; d < Dd; d += 32) s += a[d] * b[d];
        s = warp_sum(s);
        if (lane == 0) g_Mp0[i * NSd + j] = s + iou[i * NSd + j];
    }
}

__global__ void k_m1m2() {
    int r = blockIdx.x, which = blockIdx.y;
    __shared__ float w[NSd];
    int tid = threadIdx.x;
    if (tid < NSd) w[tid] = (which == 0) ? g_Mp0[r * NSd + tid] : g_Mp0[tid * NSd + r];
    __syncthreads();
    const float* E = (which == 0) ? g_e2 : g_e1;
    float* out     = (which == 0) ? g_m1 : g_m2;
    float acc = 0.f;
#pragma unroll 8
    for (int t = 0; t < NSd; t++) acc += w[t] * E[t * Dd + tid];
    out[r * Dd + tid] = acc;
}

__global__ void k_lamprep() {
    int r = blockIdx.x, which = blockIdx.y;
    const float* e = ((which == 0) ? g_e1 : g_e2) + r * Dd;
    const float* m = ((which == 0) ? g_m1 : g_m2) + r * Dd;
    float* x       = ((which == 0) ? g_x1 : g_x2) + r * Dd;
    float se = 0.f, sm = 0.f;
    for (int d = threadIdx.x; d < Dd; d += 256) {
        float ev = e[d], mv = m[d];
        se += ev * ev; sm += mv * mv;
    }
    se = warp_sum(se); sm = warp_sum(sm);
    __shared__ float rs[8], rm[8], lamS;
    int warp = threadIdx.x >> 5, lane = threadIdx.x & 31;
    if (lane == 0) { rs[warp] = se; rm[warp] = sm; }
    __syncthreads();
    if (threadIdx.x == 0) {
        float SE = 0.f, SM = 0.f;
        for (int t = 0; t < 8; t++) { SE += rs[t]; SM += rm[t]; }
        lamS = sqrtf(SE) / sqrtf(SM);
    }
    __syncthreads();
    float lam = lamS;
    for (int d = threadIdx.x; d < Dd; d += 256) x[d] = e[d] + lam * m[d];
}

__global__ void k_gemmW(const float* __restrict__ W, const float* __restrict__ b) {
    int i = blockIdx.x, which = blockIdx.y;
    const float* X = ((which == 0) ? g_x1 : g_x2) + i * Dd;
    float* Y       = ((which == 0) ? g_y1 : g_y2) + i * Dd;
    __shared__ float xs[Dd];
    for (int d = threadIdx.x; d < Dd; d += 128) xs[d] = X[d];
    __syncthreads();
    int warp = threadIdx.x >> 5, lane = threadIdx.x & 31;
    for (int o = warp; o < Dd; o += 4) {
        const float* wr = W + o * Dd;
        float s = 0.f;
#pragma unroll 4
        for (int d = lane; d < Dd; d += 32) s += xs[d] * wr[d];
        s = warp_sum(s);
        if (lane == 0) Y[o] = fmaxf(s + b[o], 0.f);
    }
}

__global__ void k_norm() {
    int r = blockIdx.x, which = blockIdx.y;
    float* y = ((which == 0) ? g_y1 : g_y2) + r * Dd;
    float s = 0.f;
    for (int d = threadIdx.x; d < Dd; d += 256) { float v = y[d]; s += v * v; }
    s = warp_sum(s);
    __shared__ float rs[8]; __shared__ float invS;
    int warp = threadIdx.x >> 5, lane = threadIdx.x & 31;
    if (lane == 0) rs[warp] = s;
    __syncthreads();
    if (threadIdx.x == 0) {
        float S = 0.f;
        for (int t = 0; t < 8; t++) S += rs[t];
        invS = 1.0f / fmaxf(sqrtf(S), 1e-12f);
    }
    __syncthreads();
    float inv = invS;
    for (int d = threadIdx.x; d < Dd; d += 256) y[d] *= inv;
}

__global__ void k_mp_thr(float* __restrict__ Mp_out, float* __restrict__ flag_out,
                         const float* __restrict__ kf, const float* __restrict__ iou,
                         const float* __restrict__ thrp) {
    int i = blockIdx.x;
    int warp = threadIdx.x >> 5, lane = threadIdx.x & 31;
    const float* a = g_y1 + i * Dd;
    float th = thrp[0];
    for (int j = warp; j < NSd; j += 4) {
        const float* b = g_y2 + j * Dd;
        float s = 0.f;
#pragma unroll 4
        for (int d = lane; d < Dd; d += 32) s += a[d] * b[d];
        s = warp_sum(s);
        if (lane == 0) {
            Mp_out[i * NSd + j] = s;
            g_v[j * NSd + i] = s;
            float fl = (kf[i * NSd + j] == -1.0f || iou[i * NSd + j] == 0.0f || s < th) ? 1.0f : 0.0f;
            flag_out[i * NSd + j] = fl;
        }
    }
}

// ---------------- phase 2: build A into the L output region; reset barrier ----------------
__global__ void k_buildA(float* __restrict__ L) {
    if (blockIdx.x == 0 && threadIdx.x == 0) { g_cnt = 0; g_gen = 0; }
    int p = blockIdx.x;
    int s1 = p % NSd, t1 = p / NSd;
    float vp = g_v[p];
    float* row = L + (size_t)p * Nn;
    for (int q = threadIdx.x; q < Nn; q += 256) {
        float val = 0.f;
        if (q == p) val = 6241.0f;
        else if (q < p) {
            int s2 = q % NSd, t2 = q / NSd;
            if (s1 != s2 && t1 != t2) val = -0.5f * (vp + g_v[q]);
        }
        row[q] = val;
    }
}

// ---------------- phase 3: persistent-kernel blocked Cholesky (NB=64) ----------------

// Device-wide barrier (all GPERS blocks guaranteed co-resident by launch_bounds).
__device__ __forceinline__ void grid_sync() {
    __threadfence();
    __syncthreads();
    if (threadIdx.x == 0) {
        int gen = atomicAdd(&g_gen, 0);
        if (atomicAdd(&g_cnt, 1) == (int)gridDim.x - 1) {
            g_cnt = 0;
            __threadfence();
            atomicExch(&g_gen, gen + 1);
        } else {
            while (atomicAdd(&g_gen, 0) == gen) { }
        }
    }
    __syncthreads();
}

// Factor 64x64 block at A (ld = Nn) in place (lower); write invL into g_inv.
// Needs 256 threads, sbuf >= 4224 floats.
__device__ void fact64(float* __restrict__ A, float* __restrict__ sbuf) {
    float* Lsh    = sbuf;            // 64*65
    float* colbuf = sbuf + 64 * 65;  // 64
    int tid = threadIdx.x;

    for (int idx = tid; idx < 64 * 64; idx += 256) {
        int r = idx >> 6, c = idx & 63;
        if (c <= r) Lsh[r * 65 + c] = A[(size_t)r * Nn + c];
    }
    __syncthreads();

    int tq = tid & 63, trow = tid >> 6;
    for (int c = 0; c < 64; c++) {
        if (tid < 64) colbuf[tid] = Lsh[tid * 65 + c];
        __syncthreads();
        float dv  = sqrtf(colbuf[c]);
        float inv = 1.0f / dv;
        float i2  = inv * inv;
        if (tid < 64) {
            if (tid > c)       Lsh[tid * 65 + c] = colbuf[tid] * inv;
            else if (tid == c) Lsh[c * 65 + c]   = dv;
        }
        if (tq > c) {
            float xq = colbuf[tq] * i2;
            for (int rr = c + 1 + trow; rr < 64; rr += 4)
                Lsh[rr * 65 + tq] -= colbuf[rr] * xq;
        }
        __syncthreads();
    }

    for (int idx = tid; idx < 64 * 64; idx += 256) {
        int r = idx >> 6, c = idx & 63;
        if (c <= r) A[(size_t)r * Nn + c] = Lsh[r * 65 + c];
    }

    if (tid < 64) colbuf[tid] = 1.0f / Lsh[tid * 65 + tid];
    __syncthreads();

    if (tid < 64) {
        int c = tid;
        float x[64];
        x[c] = colbuf[c];
        for (int jj = c + 1; jj < 64; jj++) {
            float s0 = 0.f, s1 = 0.f, s2 = 0.f, s3 = 0.f;
            int k = c;
            for (; k + 3 < jj; k += 4) {
                s0 += Lsh[jj * 65 + k + 0] * x[k + 0];
                s1 += Lsh[jj * 65 + k + 1] * x[k + 1];
                s2 += Lsh[jj * 65 + k + 2] * x[k + 2];
                s3 += Lsh[jj * 65 + k + 3] * x[k + 3];
            }
            for (; k < jj; k++) s0 += Lsh[jj * 65 + k] * x[k];
            x[jj] = -((s0 + s1) + (s2 + s3)) * colbuf[jj];
        }
        for (int jj = 0; jj < 64; jj++)
            g_inv[jj * 64 + c] = (jj >= c) ? x[jj] : 0.f;
    }
    __syncthreads();
}

// Panel solve tile: X = B * invL^T for 128 rows starting at row0 (in place).
__device__ void trsm_tile(float* __restrict__ L, int j, int M, int row0,
                          float* __restrict__ sbuf) {
    float (*As)[132] = (float(*)[132])sbuf;
    float (*Bs)[68]  = (float(*)[68])(sbuf + 16 * 132);
    float* B = L + (size_t)(j + 64) * Nn + j;
    int tid = threadIdx.x;
    float acc[4][8];
#pragma unroll
    for (int u = 0; u < 4; u++)
#pragma unroll
        for (int v = 0; v < 8; v++) acc[u][v] = 0.f;

    int ty = tid >> 3, tx = tid & 7;
    int rr = ty * 4, cc = tx * 8;

    for (int kk = 0; kk < 64; kk += 16) {
#pragma unroll
        for (int rep = 0; rep < 2; rep++) {
            int f4 = tid + rep * 256;
            int i  = f4 >> 2;
            int k4 = (f4 & 3) << 2;
            float4 av = make_float4(0.f, 0.f, 0.f, 0.f);
            if (row0 + i < M) av = *(const float4*)(B + (size_t)(row0 + i) * Nn + kk + k4);
            As[k4 + 0][i] = av.x; As[k4 + 1][i] = av.y; As[k4 + 2][i] = av.z; As[k4 + 3][i] = av.w;
        }
        {
            int ci = tid >> 2;
            int k4 = (tid & 3) << 2;
            float4 bv = *(const float4*)(g_inv + ci * 64 + kk + k4);
            Bs[k4 + 0][ci] = bv.x; Bs[k4 + 1][ci] = bv.y; Bs[k4 + 2][ci] = bv.z; Bs[k4 + 3][ci] = bv.w;
        }
        __syncthreads();
#pragma unroll
        for (int k = 0; k < 16; k++) {
            float a[4], bq[8];
            *(float4*)&a[0]  = *(const float4*)&As[k][rr];
            *(float4*)&bq[0] = *(const float4*)&Bs[k][cc];
            *(float4*)&bq[4] = *(const float4*)&Bs[k][cc + 4];
#pragma unroll
            for (int u = 0; u < 4; u++)
#pragma unroll
                for (int v = 0; v < 8; v++) acc[u][v] += a[u] * bq[v];
        }
        __syncthreads();
    }
#pragma unroll
    for (int u = 0; u < 4; u++) {
        int gr = row0 + rr + u;
        if (gr < M) {
            float* bp = B + (size_t)gr * Nn + cc;
            float4 c0, c1;
            c0.x = acc[u][0]; c0.y = acc[u][1]; c0.z = acc[u][2]; c0.w = acc[u][3];
            c1.x = acc[u][4]; c1.y = acc[u][5]; c1.z = acc[u][6]; c1.w = acc[u][7];
            *(float4*)bp = c0;
            *(float4*)(bp + 4) = c1;
        }
    }
}

// Trailing-update tile: C(128x128 at by,bx) -= P*P^T, diagonal tiles predicated.
__device__ void syrk_tile(float* __restrict__ L, int j, int M, int bx, int by,
                          float* __restrict__ sbuf) {
    float (*As)[132] = (float(*)[132])sbuf;
    float (*Bs)[132] = (float(*)[132])(sbuf + 16 * 132);
    const float* P = L + (size_t)(j + 64) * Nn + j;
    float* C       = L + (size_t)(j + 64) * Nn + (j + 64);
    int row0 = by * 128, col0 = bx * 128;
    int tid = threadIdx.x;
    float acc[8][8];
#pragma unroll
    for (int u = 0; u < 8; u++)
#pragma unroll
        for (int v = 0; v < 8; v++) acc[u][v] = 0.f;

    int ty = tid >> 4, tx = tid & 15;
    int rr = ty * 8, cc = tx * 8;

    for (int kk = 0; kk < 64; kk += 16) {
#pragma unroll
        for (int rep = 0; rep < 2; rep++) {
            int f4 = tid + rep * 256;
            int i  = f4 >> 2;
            int k4 = (f4 & 3) << 2;
            float4 av = make_float4(0.f, 0.f, 0.f, 0.f);
            float4 bv = make_float4(0.f, 0.f, 0.f, 0.f);
            if (row0 + i < M) av = *(const float4*)(P + (size_t)(row0 + i) * Nn + kk + k4);
            if (col0 + i < M) bv = *(const float4*)(P + (size_t)(col0 + i) * Nn + kk + k4);
            As[k4 + 0][i] = av.x; As[k4 + 1][i] = av.y; As[k4 + 2][i] = av.z; As[k4 + 3][i] = av.w;
            Bs[k4 + 0][i] = bv.x; Bs[k4 + 1][i] = bv.y; Bs[k4 + 2][i] = bv.z; Bs[k4 + 3][i] = bv.w;
        }
        __syncthreads();
#pragma unroll
        for (int k = 0; k < 16; k++) {
            float a[8], bq[8];
            *(float4*)&a[0]  = *(const float4*)&As[k][rr];
            *(float4*)&a[4]  = *(const float4*)&As[k][rr + 4];
            *(float4*)&bq[0] = *(const float4*)&Bs[k][cc];
            *(float4*)&bq[4] = *(const float4*)&Bs[k][cc + 4];
#pragma unroll
            for (int u = 0; u < 8; u++)
#pragma unroll
                for (int v = 0; v < 8; v++) acc[u][v] += a[u] * bq[v];
        }
        __syncthreads();
    }

    if (by > bx) {
#pragma unroll
        for (int u = 0; u < 8; u++) {
            int gr = row0 + rr + u;
            if (gr < M) {
                float* cp = C + (size_t)gr * Nn + col0 + cc;
                float4 c0 = *(float4*)cp;
                float4 c1 = *(float4*)(cp + 4);
                c0.x -= acc[u][0]; c0.y -= acc[u][1]; c0.z -= acc[u][2]; c0.w -= acc[u][3];
                c1.x -= acc[u][4]; c1.y -= acc[u][5]; c1.z -= acc[u][6]; c1.w -= acc[u][7];
                *(float4*)cp = c0;
                *(float4*)(cp + 4) = c1;
            }
        }
    } else {
#pragma unroll
        for (int u = 0; u < 8; u++) {
            int gr = row0 + rr + u;
            if (gr < M) {
#pragma unroll
                for (int v = 0; v < 8; v++) {
                    int gc = col0 + cc + v;
                    if (gc <= gr) C[(size_t)gr * Nn + gc] -= acc[u][v];
                }
            }
        }
    }
}

// The whole blocked Cholesky in ONE persistent kernel.
// Block 0 handles diag factorizations (+ only tile (0,0) of each syrk phase),
// blocks 1..G-1 share the remaining tiles — fact64 is hidden behind the syrk wave.
__global__ __launch_bounds__(256, 2) void chol_persist(float* __restrict__ L) {
    __shared__ float sbuf[4224];
    int bid = blockIdx.x;
    int G   = gridDim.x;

    if (bid == 0) fact64(L, sbuf);
    grid_sync();

    for (int j = 0; j + 64 < Nn; j += 64) {
        int M  = Nn - j - 64;
        int nt = (M + 127) >> 7;

        // ---- trsm phase ----
        for (int t = bid; t < nt; t += G)
            trsm_tile(L, j, M, t << 7, sbuf);
        grid_sync();

        // ---- syrk phase (+ fused fact64 of next diagonal on block 0) ----
        int ntS = nt * (nt + 1) / 2;
        if (bid == 0) {
            syrk_tile(L, j, M, 0, 0, sbuf);
            __syncthreads();
            fact64(L + (size_t)(j + 64) * Nn + (j + 64), sbuf);
        } else {
            for (int s = bid; s < ntS; s += G - 1) {
                int by = (int)((sqrtf(8.0f * (float)s + 1.0f) - 1.0f) * 0.5f);
                while ((by + 1) * (by + 2) / 2 <= s) by++;
                while (by * (by + 1) / 2 > s) by--;
                int bx = s - ((by * (by + 1)) >> 1);
                syrk_tile(L, j, M, bx, by, sbuf);
            }
        }
        grid_sync();
    }
}

// ---------------- launch ----------------
extern "C" void kernel_launch(void* const* d_in, const int* in_sizes, int n_in,
                              void* d_out, int out_size) {
    (void)in_sizes; (void)n_in; (void)out_size;
    const float* U_src = (const float*)d_in[0];
    const float* U_tgt = (const float*)d_in[1];
    const float* kf    = (const float*)d_in[2];
    const float* thrp  = (const float*)d_in[3];
    const float* iou   = (const float*)d_in[4];
    const float* W     = (const float*)d_in[5];
    const float* b     = (const float*)d_in[6];

    float* out      = (float*)d_out;
    float* Mp_out   = out;                       // [80*80]
    float* Lm       = out + NSd * NSd;           // [6400*6400]
    float* flag_out = out + NSd * NSd + Nn * Nn; // [80*80]

    k_transpose<<<(NSd * Dd + 255) / 256, 256>>>(U_src, U_tgt);
    k_mp0<<<NSd, 128>>>(iou);
    k_m1m2<<<dim3(NSd, 2), 512>>>();
    k_lamprep<<<dim3(NSd, 2), 256>>>();
    k_gemmW<<<dim3(NSd, 2), 128>>>(W, b);
    k_norm<<<dim3(NSd, 2), 256>>>();
    k_mp_thr<<<NSd, 128>>>(Mp_out, flag_out, kf, iou, thrp);
    k_buildA<<<Nn, 256>>>(Lm);          // also resets the grid barrier

    chol_persist<<<GPERS, 256>>>(Lm);   // the entire Cholesky, one launch
}